// round 2
// baseline (speedup 1.0000x reference)
#include <cuda_runtime.h>

#define NIMG 256            // 8 batch * 32 channels
#define LL_IST (262*262)    // per-image stride of ll ping-pong buffers

// ---------------- filter banks (db6, pytorch_wavelets conventions) ----------------
__constant__ float c_ana0[12] = {
  0.11154074335008017f, 0.4946238903983854f, 0.7511339080215775f, 0.3152503517092432f,
  -0.22626469396516913f, -0.12976686756709563f, 0.09750160558707936f, 0.02752286553001629f,
  -0.031582039318031156f, 0.0005538422009938016f, 0.004777257511010651f, -0.00107730108499558f };
__constant__ float c_ana1[12] = {
  -0.00107730108499558f, -0.004777257511010651f, 0.0005538422009938016f, 0.031582039318031156f,
  0.02752286553001629f, -0.09750160558707936f, -0.12976686756709563f, 0.22626469396516913f,
  0.3152503517092432f, -0.7511339080215775f, 0.4946238903983854f, -0.11154074335008017f };
__constant__ float c_syn0[12] = {
  -0.00107730108499558f, 0.004777257511010651f, 0.0005538422009938016f, -0.031582039318031156f,
  0.02752286553001629f, 0.09750160558707936f, -0.12976686756709563f, -0.22626469396516913f,
  0.3152503517092432f, 0.7511339080215775f, 0.4946238903983854f, 0.11154074335008017f };
__constant__ float c_syn1[12] = {
  -0.11154074335008017f, 0.4946238903983854f, -0.7511339080215775f, 0.3152503517092432f,
  0.22626469396516913f, -0.12976686756709563f, -0.09750160558707936f, 0.02752286553001629f,
  0.031582039318031156f, 0.0005538422009938016f, -0.004777257511010651f, -0.00107730108499558f };

// ---------------- scratch (device globals; no allocation in kernel_launch) ----------------
__device__ float g_tmpA[NIMG * 512 * 261];
__device__ float g_tmpB[NIMG * 512 * 261];
__device__ float g_llA [NIMG * LL_IST];
__device__ float g_llB [NIMG * LL_IST];
__device__ float g_yh1 [NIMG * 3 * 261 * 261];
__device__ float g_yh2 [NIMG * 3 * 136 * 136];
__device__ float g_yh3 [NIMG * 3 * 73 * 73];
__device__ float g_yl4 [NIMG * 42 * 42];
__device__ float g_yh4 [NIMG * 3 * 42 * 42];
__device__ float g_yl4t[NIMG * 42 * 42];
__device__ float g_yh4t[NIMG * 3 * 42 * 42];

__device__ __forceinline__ int refl(int j, int N) {
    // single symmetric (edge-inclusive) reflection; pad <= 11 < N always
    j = (j < 0) ? (-1 - j) : j;
    j = (j >= N) ? (2 * N - 1 - j) : j;
    return j;
}

// ---------- analysis along width: in (NIMG, H, Win) -> lo,hi (NIMG, H, Wout), pl=10 ----------
__global__ void __launch_bounds__(256)
k_afb_rows(const float* __restrict__ in, float* __restrict__ lo, float* __restrict__ hi,
           int H, int Win, int in_ist, int in_rst, int Wout, int o_ist)
{
    int idx = blockIdx.x * 256 + threadIdx.x;
    int total = NIMG * H * Wout;
    if (idx >= total) return;
    int t   = idx % Wout;
    int r   = (idx / Wout) % H;
    int img = idx / (Wout * H);
    const float* row = in + (size_t)img * in_ist + (size_t)r * in_rst;
    float a0 = 0.f, a1 = 0.f;
    int j0 = 2 * t - 10;
#pragma unroll
    for (int k = 0; k < 12; k++) {
        float v = row[refl(j0 + k, Win)];
        a0 = fmaf(v, c_ana0[k], a0);
        a1 = fmaf(v, c_ana1[k], a1);
    }
    int o = img * o_ist + r * Wout + t;
    lo[o] = a0;
    hi[o] = a1;
}

// ---------- analysis along height: in (NIMG, Hin, W) -> lo,hi (NIMG, Hout, W), pl=10 ----------
__global__ void __launch_bounds__(256)
k_afb_cols(const float* __restrict__ in, float* __restrict__ lo, float* __restrict__ hi,
           int Hin, int W, int in_ist, int Hout, int lo_ist, int hi_ist)
{
    int idx = blockIdx.x * 256 + threadIdx.x;
    int total = NIMG * Hout * W;
    if (idx >= total) return;
    int c   = idx % W;
    int t   = (idx / W) % Hout;
    int img = idx / (W * Hout);
    const float* im = in + (size_t)img * in_ist + c;
    float a0 = 0.f, a1 = 0.f;
    int j0 = 2 * t - 10;
#pragma unroll
    for (int k = 0; k < 12; k++) {
        float v = im[(size_t)refl(j0 + k, Hin) * W];
        a0 = fmaf(v, c_ana0[k], a0);
        a1 = fmaf(v, c_ana1[k], a1);
    }
    lo[(size_t)img * lo_ist + (size_t)t * W + c] = a0;
    hi[(size_t)img * hi_ist + (size_t)t * W + c] = a1;
}

// ---------- synthesis along height: a,b (NIMG, N, W) -> out (NIMG, Hout=2N-10, W) ----------
__global__ void __launch_bounds__(256)
k_sfb_cols(const float* __restrict__ a, const float* __restrict__ b, float* __restrict__ out,
           int N, int W, int a_ist, int a_rst, int b_ist, int Hout)
{
    int idx = blockIdx.x * 256 + threadIdx.x;
    int total = NIMG * Hout * W;
    if (idx >= total) return;
    int c   = idx % W;
    int t   = (idx / W) % Hout;
    int img = idx / (W * Hout);
    const float* pa = a + (size_t)img * a_ist + c;
    const float* pb = b + (size_t)img * b_ist + c;
    int mb = t >> 1;
    int kb = 2 * mb + 1 - t;       // 1 if t even else 0
    float acc = 0.f;
#pragma unroll
    for (int dm = 0; dm < 6; dm++) {
        int m = mb + dm;
        if (m < N) {
            int k = kb + 2 * dm;
            acc = fmaf(pa[(size_t)m * a_rst], c_syn0[k], acc);
            acc = fmaf(pb[(size_t)m * W],     c_syn1[k], acc);
        }
    }
    out[(size_t)img * (Hout * W) + (size_t)t * W + c] = acc;
}

// ---------- synthesis along width: a,b (NIMG, H, N) -> out (NIMG, H, Wout=2N-10) ----------
__global__ void __launch_bounds__(256)
k_sfb_rows(const float* __restrict__ a, const float* __restrict__ b, float* __restrict__ out,
           int H, int N, int Wout, int o_ist, int o_rst)
{
    int idx = blockIdx.x * 256 + threadIdx.x;
    int total = NIMG * H * Wout;
    if (idx >= total) return;
    int t   = idx % Wout;
    int r   = (idx / Wout) % H;
    int img = idx / (Wout * H);
    const float* pa = a + (size_t)(img * H + r) * N;
    const float* pb = b + (size_t)(img * H + r) * N;
    int mb = t >> 1;
    int kb = 2 * mb + 1 - t;
    float acc = 0.f;
#pragma unroll
    for (int dm = 0; dm < 6; dm++) {
        int m = mb + dm;
        if (m < N) {
            int k = kb + 2 * dm;
            acc = fmaf(pa[m], c_syn0[k], acc);
            acc = fmaf(pb[m], c_syn1[k], acc);
        }
    }
    out[(size_t)img * o_ist + (size_t)r * o_rst + t] = acc;
}

// ---------- per-pixel channel mixing at the coarsest scale ----------
__global__ void __launch_bounds__(256)
k_mix_yl(const float* __restrict__ in, const float* __restrict__ w, float* __restrict__ out)
{
    // in (8,32,1764), w (32,32,1764), out (8,32,1764)
    int idx = blockIdx.x * 256 + threadIdx.x;
    if (idx >= 8 * 32 * 1764) return;
    int p = idx % 1764;
    int o = (idx / 1764) % 32;
    int bB = idx / (1764 * 32);
    float acc = 0.f;
#pragma unroll 8
    for (int i = 0; i < 32; i++)
        acc = fmaf(in[(bB * 32 + i) * 1764 + p], w[(i * 32 + o) * 1764 + p], acc);
    out[idx] = acc;
}

__global__ void __launch_bounds__(256)
k_mix_yh(const float* __restrict__ in, const float* __restrict__ w, float* __restrict__ out)
{
    // in (8,32,3,1764), w (32,32,3,1764), out (8,32,3,1764)
    int idx = blockIdx.x * 256 + threadIdx.x;
    if (idx >= 8 * 32 * 3 * 1764) return;
    int p = idx % 1764;
    int c = (idx / 1764) % 3;
    int o = (idx / (1764 * 3)) % 32;
    int bB = idx / (1764 * 3 * 32);
    float acc = 0.f;
#pragma unroll 8
    for (int i = 0; i < 32; i++)
        acc = fmaf(in[((bB * 32 + i) * 3 + c) * 1764 + p],
                   w [((i * 32 + o) * 3 + c) * 1764 + p], acc);
    out[idx] = acc;
}

static inline int grd(long n) { return (int)((n + 255) / 256); }

extern "C" void kernel_launch(void* const* d_in, const int* in_sizes, int n_in,
                              void* d_out, int out_size)
{
    const float* x    = (const float*)d_in[0];
    const float* w_yl = (const float*)d_in[1];
    const float* w_yh = (const float*)d_in[2];
    float* out = (float*)d_out;

    float *tmpA, *tmpB, *llA, *llB, *yh1, *yh2, *yh3, *yl4, *yh4, *yl4t, *yh4t;
    cudaGetSymbolAddress((void**)&tmpA, g_tmpA);
    cudaGetSymbolAddress((void**)&tmpB, g_tmpB);
    cudaGetSymbolAddress((void**)&llA,  g_llA);
    cudaGetSymbolAddress((void**)&llB,  g_llB);
    cudaGetSymbolAddress((void**)&yh1,  g_yh1);
    cudaGetSymbolAddress((void**)&yh2,  g_yh2);
    cudaGetSymbolAddress((void**)&yh3,  g_yh3);
    cudaGetSymbolAddress((void**)&yl4,  g_yl4);
    cudaGetSymbolAddress((void**)&yh4,  g_yh4);
    cudaGetSymbolAddress((void**)&yl4t, g_yl4t);
    cudaGetSymbolAddress((void**)&yh4t, g_yh4t);

    // ================= forward DWT =================
    // level 1: 512x512 -> 261x261
    k_afb_rows<<<grd((long)NIMG*512*261),256>>>(x, tmpA, tmpB, 512, 512, 512*512, 512, 261, 512*261);
    k_afb_cols<<<grd((long)NIMG*261*261),256>>>(tmpA, llA, yh1,                512, 261, 512*261, 261, LL_IST, 204363);
    k_afb_cols<<<grd((long)NIMG*261*261),256>>>(tmpB, yh1+68121, yh1+2*68121,  512, 261, 512*261, 261, 204363, 204363);
    // level 2: 261 -> 136
    k_afb_rows<<<grd((long)NIMG*261*136),256>>>(llA, tmpA, tmpB, 261, 261, LL_IST, 261, 136, 261*136);
    k_afb_cols<<<grd((long)NIMG*136*136),256>>>(tmpA, llB, yh2,                261, 136, 261*136, 136, LL_IST, 55488);
    k_afb_cols<<<grd((long)NIMG*136*136),256>>>(tmpB, yh2+18496, yh2+2*18496,  261, 136, 261*136, 136, 55488, 55488);
    // level 3: 136 -> 73
    k_afb_rows<<<grd((long)NIMG*136*73),256>>>(llB, tmpA, tmpB, 136, 136, LL_IST, 136, 73, 136*73);
    k_afb_cols<<<grd((long)NIMG*73*73),256>>>(tmpA, llA, yh3,               136, 73, 136*73, 73, LL_IST, 15987);
    k_afb_cols<<<grd((long)NIMG*73*73),256>>>(tmpB, yh3+5329, yh3+2*5329,   136, 73, 136*73, 73, 15987, 15987);
    // level 4: 73 -> 42
    k_afb_rows<<<grd((long)NIMG*73*42),256>>>(llA, tmpA, tmpB, 73, 73, LL_IST, 73, 42, 73*42);
    k_afb_cols<<<grd((long)NIMG*42*42),256>>>(tmpA, yl4, yh4,               73, 42, 73*42, 42, 1764, 5292);
    k_afb_cols<<<grd((long)NIMG*42*42),256>>>(tmpB, yh4+1764, yh4+2*1764,   73, 42, 73*42, 42, 5292, 5292);

    // ================= channel mixing =================
    k_mix_yl<<<grd((long)8*32*1764),   256>>>(yl4, w_yl, yl4t);
    k_mix_yh<<<grd((long)8*32*3*1764), 256>>>(yh4, w_yh, yh4t);

    // ================= inverse DWT =================
    // level 4: 42 -> 74x74
    k_sfb_cols<<<grd((long)NIMG*74*42),256>>>(yl4t,      yh4t,        tmpA, 42, 42, 1764, 42, 5292, 74);
    k_sfb_cols<<<grd((long)NIMG*74*42),256>>>(yh4t+1764, yh4t+2*1764, tmpB, 42, 42, 5292, 42, 5292, 74);
    k_sfb_rows<<<grd((long)NIMG*74*74),256>>>(tmpA, tmpB, llA, 74, 42, 74, LL_IST, 74);
    // level 3: crop 74->73, -> 136x136
    k_sfb_cols<<<grd((long)NIMG*136*73),256>>>(llA,       yh3,         tmpA, 73, 73, LL_IST, 74, 15987, 136);
    k_sfb_cols<<<grd((long)NIMG*136*73),256>>>(yh3+5329,  yh3+2*5329,  tmpB, 73, 73, 15987,  73, 15987, 136);
    k_sfb_rows<<<grd((long)NIMG*136*136),256>>>(tmpA, tmpB, llB, 136, 73, 136, LL_IST, 136);
    // level 2: 136 -> 262x262
    k_sfb_cols<<<grd((long)NIMG*262*136),256>>>(llB,        yh2,         tmpA, 136, 136, LL_IST, 136, 55488, 262);
    k_sfb_cols<<<grd((long)NIMG*262*136),256>>>(yh2+18496,  yh2+2*18496, tmpB, 136, 136, 55488,  136, 55488, 262);
    k_sfb_rows<<<grd((long)NIMG*262*262),256>>>(tmpA, tmpB, llA, 262, 136, 262, LL_IST, 262);
    // level 1: crop 262->261, -> 512x512 into d_out
    k_sfb_cols<<<grd((long)NIMG*512*261),256>>>(llA,        yh1,         tmpA, 261, 261, LL_IST, 262, 204363, 512);
    k_sfb_cols<<<grd((long)NIMG*512*261),256>>>(yh1+68121,  yh1+2*68121, tmpB, 261, 261, 204363, 261, 204363, 512);
    k_sfb_rows<<<grd((long)NIMG*512*512),256>>>(tmpA, tmpB, out, 512, 261, 512, 512*512, 512);
}

// round 7
// speedup vs baseline: 2.4058x; 2.4058x over previous
#include <cuda_runtime.h>

#define NIMG 256            // 8 batch * 32 channels
#define LL_IST (262*262)    // per-image stride of ll ping-pong buffers

// ---------------- filter banks (db6, pytorch_wavelets conventions) ----------------
__constant__ float c_ana0[12] = {
  0.11154074335008017f, 0.4946238903983854f, 0.7511339080215775f, 0.3152503517092432f,
  -0.22626469396516913f, -0.12976686756709563f, 0.09750160558707936f, 0.02752286553001629f,
  -0.031582039318031156f, 0.0005538422009938016f, 0.004777257511010651f, -0.00107730108499558f };
__constant__ float c_ana1[12] = {
  -0.00107730108499558f, -0.004777257511010651f, 0.0005538422009938016f, 0.031582039318031156f,
  0.02752286553001629f, -0.09750160558707936f, -0.12976686756709563f, 0.22626469396516913f,
  0.3152503517092432f, -0.7511339080215775f, 0.4946238903983854f, -0.11154074335008017f };
__constant__ float c_syn0[12] = {
  -0.00107730108499558f, 0.004777257511010651f, 0.0005538422009938016f, -0.031582039318031156f,
  0.02752286553001629f, 0.09750160558707936f, -0.12976686756709563f, -0.22626469396516913f,
  0.3152503517092432f, 0.7511339080215775f, 0.4946238903983854f, 0.11154074335008017f };
__constant__ float c_syn1[12] = {
  -0.11154074335008017f, 0.4946238903983854f, -0.7511339080215775f, 0.3152503517092432f,
  0.22626469396516913f, -0.12976686756709563f, -0.09750160558707936f, 0.02752286553001629f,
  0.031582039318031156f, 0.0005538422009938016f, -0.004777257511010651f, -0.00107730108499558f };

// ---------------- scratch (device globals; no allocation in kernel_launch) ----------------
__device__ float g_tmpA[NIMG * 512 * 261];
__device__ float g_tmpB[NIMG * 512 * 261];
__device__ float g_llA [NIMG * LL_IST];
__device__ float g_llB [NIMG * LL_IST];
__device__ float g_yh1 [NIMG * 3 * 261 * 261];
__device__ float g_yh2 [NIMG * 3 * 136 * 136];
__device__ float g_yh3 [NIMG * 3 * 73 * 73];
__device__ float g_yl4 [NIMG * 42 * 42];
__device__ float g_yh4 [NIMG * 3 * 42 * 42];
__device__ float g_yl4t[NIMG * 42 * 42];
__device__ float g_yh4t[NIMG * 3 * 42 * 42];

__device__ __forceinline__ int refl(int j, int N) {
    j = (j < 0) ? (-1 - j) : j;
    j = (j >= N) ? (2 * N - 1 - j) : j;
    return j;
}

// ---------- analysis along width: in (NIMG, H, WIN) -> lo,hi (NIMG, H, WOUT) ----------
template<int H, int WIN, int WOUT, int IN_IST, int IN_RST, int O_IST>
__global__ void __launch_bounds__(256)
k_afb_rows(const float* __restrict__ in, float* __restrict__ lo, float* __restrict__ hi)
{
    int idx = blockIdx.x * 256 + threadIdx.x;
    if (idx >= H * WOUT) return;
    int t   = idx % WOUT;           // compile-time divisor
    int r   = idx / WOUT;
    int img = blockIdx.y;
    const float* row = in + (size_t)img * IN_IST + (size_t)r * IN_RST;
    float a0 = 0.f, a1 = 0.f;
    int j0 = 2 * t - 10;
    if (t >= 5 && 2 * t + 1 < WIN) {            // interior: pure imm-offset loads
        const float* p = row + j0;
#pragma unroll
        for (int k = 0; k < 12; k++) {
            float v = p[k];
            a0 = fmaf(v, c_ana0[k], a0);
            a1 = fmaf(v, c_ana1[k], a1);
        }
    } else {
#pragma unroll
        for (int k = 0; k < 12; k++) {
            float v = row[refl(j0 + k, WIN)];
            a0 = fmaf(v, c_ana0[k], a0);
            a1 = fmaf(v, c_ana1[k], a1);
        }
    }
    int o = img * O_IST + r * WOUT + t;
    lo[o] = a0;
    hi[o] = a1;
}

// ---------- analysis along height: in (NIMG, HIN, W) -> lo,hi (NIMG, HOUT, W) ----------
template<int HIN, int W, int IN_IST, int HOUT, int LO_IST, int HI_IST>
__global__ void __launch_bounds__(256)
k_afb_cols(const float* __restrict__ in, float* __restrict__ lo, float* __restrict__ hi)
{
    int idx = blockIdx.x * 256 + threadIdx.x;
    if (idx >= HOUT * W) return;
    int c   = idx % W;
    int t   = idx / W;
    int img = blockIdx.y;
    const float* im = in + (size_t)img * IN_IST + c;
    float a0 = 0.f, a1 = 0.f;
    int j0 = 2 * t - 10;
    if (t >= 5 && 2 * t + 1 < HIN) {
        const float* p = im + (size_t)j0 * W;
#pragma unroll
        for (int k = 0; k < 12; k++) {
            float v = p[k * W];                  // compile-time stride
            a0 = fmaf(v, c_ana0[k], a0);
            a1 = fmaf(v, c_ana1[k], a1);
        }
    } else {
#pragma unroll
        for (int k = 0; k < 12; k++) {
            float v = im[(size_t)refl(j0 + k, HIN) * W];
            a0 = fmaf(v, c_ana0[k], a0);
            a1 = fmaf(v, c_ana1[k], a1);
        }
    }
    lo[(size_t)img * LO_IST + t * W + c] = a0;
    hi[(size_t)img * HI_IST + t * W + c] = a1;
}

// ---------- synthesis along height, output-pair threads ----------
// a,b (NIMG, N, *) -> out (NIMG, 2N-10, W); thread computes rows (2u, 2u+1)
template<int N, int W, int A_IST, int A_RST, int B_IST>
__global__ void __launch_bounds__(256)
k_sfb_cols(const float* __restrict__ a, const float* __restrict__ b, float* __restrict__ out)
{
    constexpr int NP = N - 5;            // output pairs
    constexpr int HOUT = 2 * N - 10;
    int idx = blockIdx.x * 256 + threadIdx.x;
    if (idx >= NP * W) return;
    int c   = idx % W;
    int u   = idx / W;
    int img = blockIdx.y;
    const float* pa = a + (size_t)img * A_IST + (size_t)u * A_RST + c;
    const float* pb = b + (size_t)img * B_IST + (size_t)u * W + c;
    float e = 0.f, o = 0.f;              // even row (taps 1,3,..11), odd row (taps 0,2,..10)
#pragma unroll
    for (int dm = 0; dm < 6; dm++) {
        float va = pa[(size_t)dm * A_RST];
        float vb = pb[(size_t)dm * W];
        e = fmaf(va, c_syn0[1 + 2 * dm], e);
        e = fmaf(vb, c_syn1[1 + 2 * dm], e);
        o = fmaf(va, c_syn0[2 * dm], o);
        o = fmaf(vb, c_syn1[2 * dm], o);
    }
    float* po = out + (size_t)img * (HOUT * W) + (size_t)(2 * u) * W + c;
    po[0] = e;
    po[W] = o;
}

// ---------- synthesis along width, output-pair threads, float2 store ----------
// a,b (NIMG, H, N) contiguous -> out (NIMG, H, 2N-10)
template<int H, int N, int O_IST, int O_RST>
__global__ void __launch_bounds__(256)
k_sfb_rows(const float* __restrict__ a, const float* __restrict__ b, float* __restrict__ out)
{
    constexpr int NP = N - 5;
    int idx = blockIdx.x * 256 + threadIdx.x;
    if (idx >= H * NP) return;
    int u   = idx % NP;
    int r   = idx / NP;
    int img = blockIdx.y;
    const float* pa = a + ((size_t)img * H + r) * N + u;
    const float* pb = b + ((size_t)img * H + r) * N + u;
    float e = 0.f, o = 0.f;
#pragma unroll
    for (int dm = 0; dm < 6; dm++) {
        float va = pa[dm];
        float vb = pb[dm];
        e = fmaf(va, c_syn0[1 + 2 * dm], e);
        e = fmaf(vb, c_syn1[1 + 2 * dm], e);
        o = fmaf(va, c_syn0[2 * dm], o);
        o = fmaf(vb, c_syn1[2 * dm], o);
    }
    float2 v2 = make_float2(e, o);
    *reinterpret_cast<float2*>(out + (size_t)img * O_IST + (size_t)r * O_RST + 2 * u) = v2;
}

// ---------- per-pixel channel mixing at the coarsest scale ----------
__global__ void __launch_bounds__(256)
k_mix_yl(const float* __restrict__ in, const float* __restrict__ w, float* __restrict__ out)
{
    int idx = blockIdx.x * 256 + threadIdx.x;
    if (idx >= 8 * 32 * 1764) return;
    int p = idx % 1764;
    int o = (idx / 1764) % 32;
    int bB = idx / (1764 * 32);
    float acc = 0.f;
#pragma unroll
    for (int i = 0; i < 32; i++)
        acc = fmaf(in[(bB * 32 + i) * 1764 + p], w[(i * 32 + o) * 1764 + p], acc);
    out[idx] = acc;
}

__global__ void __launch_bounds__(256)
k_mix_yh(const float* __restrict__ in, const float* __restrict__ w, float* __restrict__ out)
{
    int idx = blockIdx.x * 256 + threadIdx.x;
    if (idx >= 8 * 32 * 3 * 1764) return;
    int p = idx % 1764;
    int c = (idx / 1764) % 3;
    int o = (idx / (1764 * 3)) % 32;
    int bB = idx / (1764 * 3 * 32);
    float acc = 0.f;
#pragma unroll
    for (int i = 0; i < 32; i++)
        acc = fmaf(in[((bB * 32 + i) * 3 + c) * 1764 + p],
                   w [((i * 32 + o) * 3 + c) * 1764 + p], acc);
    out[idx] = acc;
}

static inline dim3 grd2(long n) { return dim3((unsigned)((n + 255) / 256), NIMG, 1); }
static inline int  grd1(long n) { return (int)((n + 255) / 256); }

extern "C" void kernel_launch(void* const* d_in, const int* in_sizes, int n_in,
                              void* d_out, int out_size)
{
    const float* x    = (const float*)d_in[0];
    const float* w_yl = (const float*)d_in[1];
    const float* w_yh = (const float*)d_in[2];
    float* out = (float*)d_out;

    float *tmpA, *tmpB, *llA, *llB, *yh1, *yh2, *yh3, *yl4, *yh4, *yl4t, *yh4t;
    cudaGetSymbolAddress((void**)&tmpA, g_tmpA);
    cudaGetSymbolAddress((void**)&tmpB, g_tmpB);
    cudaGetSymbolAddress((void**)&llA,  g_llA);
    cudaGetSymbolAddress((void**)&llB,  g_llB);
    cudaGetSymbolAddress((void**)&yh1,  g_yh1);
    cudaGetSymbolAddress((void**)&yh2,  g_yh2);
    cudaGetSymbolAddress((void**)&yh3,  g_yh3);
    cudaGetSymbolAddress((void**)&yl4,  g_yl4);
    cudaGetSymbolAddress((void**)&yh4,  g_yh4);
    cudaGetSymbolAddress((void**)&yl4t, g_yl4t);
    cudaGetSymbolAddress((void**)&yh4t, g_yh4t);

    // ================= forward DWT =================
    // level 1: 512x512 -> 261x261
    k_afb_rows<512,512,261, 512*512, 512, 512*261><<<grd2(512L*261),256>>>(x, tmpA, tmpB);
    k_afb_cols<512,261, 512*261, 261, LL_IST, 204363><<<grd2(261L*261),256>>>(tmpA, llA, yh1);
    k_afb_cols<512,261, 512*261, 261, 204363, 204363><<<grd2(261L*261),256>>>(tmpB, yh1+68121, yh1+2*68121);
    // level 2: 261 -> 136
    k_afb_rows<261,261,136, LL_IST, 261, 261*136><<<grd2(261L*136),256>>>(llA, tmpA, tmpB);
    k_afb_cols<261,136, 261*136, 136, LL_IST, 55488><<<grd2(136L*136),256>>>(tmpA, llB, yh2);
    k_afb_cols<261,136, 261*136, 136, 55488, 55488><<<grd2(136L*136),256>>>(tmpB, yh2+18496, yh2+2*18496);
    // level 3: 136 -> 73
    k_afb_rows<136,136,73, LL_IST, 136, 136*73><<<grd2(136L*73),256>>>(llB, tmpA, tmpB);
    k_afb_cols<136,73, 136*73, 73, LL_IST, 15987><<<grd2(73L*73),256>>>(tmpA, llA, yh3);
    k_afb_cols<136,73, 136*73, 73, 15987, 15987><<<grd2(73L*73),256>>>(tmpB, yh3+5329, yh3+2*5329);
    // level 4: 73 -> 42
    k_afb_rows<73,73,42, LL_IST, 73, 73*42><<<grd2(73L*42),256>>>(llA, tmpA, tmpB);
    k_afb_cols<73,42, 73*42, 42, 1764, 5292><<<grd2(42L*42),256>>>(tmpA, yl4, yh4);
    k_afb_cols<73,42, 73*42, 42, 5292, 5292><<<grd2(42L*42),256>>>(tmpB, yh4+1764, yh4+2*1764);

    // ================= channel mixing =================
    k_mix_yl<<<grd1(8L*32*1764),   256>>>(yl4, w_yl, yl4t);
    k_mix_yh<<<grd1(8L*32*3*1764), 256>>>(yh4, w_yh, yh4t);

    // ================= inverse DWT =================
    // level 4: 42 -> 74x74
    k_sfb_cols<42,42, 1764, 42, 5292><<<grd2(37L*42),256>>>(yl4t,      yh4t,        tmpA);
    k_sfb_cols<42,42, 5292, 42, 5292><<<grd2(37L*42),256>>>(yh4t+1764, yh4t+2*1764, tmpB);
    k_sfb_rows<74,42, LL_IST, 74><<<grd2(74L*37),256>>>(tmpA, tmpB, llA);
    // level 3: crop 74->73, -> 136x136
    k_sfb_cols<73,73, LL_IST, 74, 15987><<<grd2(68L*73),256>>>(llA,      yh3,        tmpA);
    k_sfb_cols<73,73, 15987, 73, 15987><<<grd2(68L*73),256>>>(yh3+5329, yh3+2*5329, tmpB);
    k_sfb_rows<136,73, LL_IST, 136><<<grd2(136L*68),256>>>(tmpA, tmpB, llB);
    // level 2: 136 -> 262x262
    k_sfb_cols<136,136, LL_IST, 136, 55488><<<grd2(131L*136),256>>>(llB,       yh2,         tmpA);
    k_sfb_cols<136,136, 55488, 136, 55488><<<grd2(131L*136),256>>>(yh2+18496, yh2+2*18496, tmpB);
    k_sfb_rows<262,136, LL_IST, 262><<<grd2(262L*131),256>>>(tmpA, tmpB, llA);
    // level 1: crop 262->261, -> 512x512 into d_out
    k_sfb_cols<261,261, LL_IST, 262, 204363><<<grd2(256L*261),256>>>(llA,       yh1,         tmpA);
    k_sfb_cols<261,261, 204363, 261, 204363><<<grd2(256L*261),256>>>(yh1+68121, yh1+2*68121, tmpB);
    k_sfb_rows<512,261, 512*512, 512><<<grd2(512L*256),256>>>(tmpA, tmpB, out);
}

// round 12
// speedup vs baseline: 3.4138x; 1.4190x over previous
#include <cuda_runtime.h>

#define NIMG 256            // 8 batch * 32 channels

// ---------------- filter banks (db6, pytorch_wavelets conventions) ----------------
__constant__ float c_ana0[12] = {
  0.11154074335008017f, 0.4946238903983854f, 0.7511339080215775f, 0.3152503517092432f,
  -0.22626469396516913f, -0.12976686756709563f, 0.09750160558707936f, 0.02752286553001629f,
  -0.031582039318031156f, 0.0005538422009938016f, 0.004777257511010651f, -0.00107730108499558f };
__constant__ float c_ana1[12] = {
  -0.00107730108499558f, -0.004777257511010651f, 0.0005538422009938016f, 0.031582039318031156f,
  0.02752286553001629f, -0.09750160558707936f, -0.12976686756709563f, 0.22626469396516913f,
  0.3152503517092432f, -0.7511339080215775f, 0.4946238903983854f, -0.11154074335008017f };
__constant__ float c_syn0[12] = {
  -0.00107730108499558f, 0.004777257511010651f, 0.0005538422009938016f, -0.031582039318031156f,
  0.02752286553001629f, 0.09750160558707936f, -0.12976686756709563f, -0.22626469396516913f,
  0.3152503517092432f, 0.7511339080215775f, 0.4946238903983854f, 0.11154074335008017f };
__constant__ float c_syn1[12] = {
  -0.11154074335008017f, 0.4946238903983854f, -0.7511339080215775f, 0.3152503517092432f,
  0.22626469396516913f, -0.12976686756709563f, -0.09750160558707936f, 0.02752286553001629f,
  0.031582039318031156f, 0.0005538422009938016f, -0.004777257511010651f, -0.00107730108499558f };

// ---------------- scratch (device globals; even row strides everywhere) ----------------
// tmp buffers sized for the largest level (512 rows x 262 stride) + margin reads
__device__ float g_tmpA[NIMG * 512 * 262];
__device__ float g_tmpB[NIMG * 512 * 262];
__device__ float g_llA [NIMG * 68644];          // 262*262
__device__ float g_llB [NIMG * 18496];          // 136*136
__device__ float g_yh1 [NIMG * 3 * 68644];      // rst 262, sb 68644
__device__ float g_yh2 [NIMG * 3 * 18496];      // rst 136
__device__ float g_yh3 [NIMG * 3 * 5476];       // rst 74,  sb 5476
__device__ float g_yh4 [NIMG * 3 * 1764];       // rst 42
__device__ float g_yl4 [NIMG * 1764];
__device__ float g_yl4t[NIMG * 1764];
__device__ float g_yh4t[NIMG * 3 * 1764];

__device__ __forceinline__ int refl(int j, int N) {
    j = (j < 0) ? (-1 - j) : j;
    j = (j >= N) ? (2 * N - 1 - j) : j;
    return j;
}

// ---------- analysis along width, output-pair threads, float2 loads ----------
// in (NIMG, H, WIN) -> lo,hi (NIMG, H, WOUT) with row stride O_RST (>= WOUT, even)
template<int H, int WIN, int WOUT, int IN_IST, int IN_RST, int O_RST, int O_IST>
__global__ void __launch_bounds__(256)
k_afb_rows(const float* __restrict__ in, float* __restrict__ lo, float* __restrict__ hi)
{
    constexpr int NP = (WOUT + 1) / 2;
    int idx = blockIdx.x * 256 + threadIdx.x;
    if (idx >= H * NP) return;
    int pi = idx % NP;
    int r  = idx / NP;
    int img = blockIdx.y;
    const float* row = in + (size_t)img * IN_IST + (size_t)r * IN_RST;
    int t0 = 2 * pi;
    int j0 = 4 * pi - 10;
    float w[14];
    if (j0 >= 0 && j0 + 13 < WIN) {
        const float2* p = reinterpret_cast<const float2*>(row + j0);   // j0 even, base even
#pragma unroll
        for (int k = 0; k < 7; k++) { float2 v = p[k]; w[2*k] = v.x; w[2*k+1] = v.y; }
    } else {
#pragma unroll
        for (int k = 0; k < 14; k++) w[k] = row[refl(j0 + k, WIN)];
    }
    float a0 = 0.f, a1 = 0.f, b0 = 0.f, b1 = 0.f;
#pragma unroll
    for (int k = 0; k < 12; k++) {
        a0 = fmaf(w[k],     c_ana0[k], a0);
        a1 = fmaf(w[k],     c_ana1[k], a1);
        b0 = fmaf(w[k + 2], c_ana0[k], b0);
        b1 = fmaf(w[k + 2], c_ana1[k], b1);
    }
    float* plo = lo + (size_t)img * O_IST + (size_t)r * O_RST + t0;
    float* phi = hi + (size_t)img * O_IST + (size_t)r * O_RST + t0;
    *reinterpret_cast<float2*>(plo) = make_float2(a0, b0);   // t0+1==WOUT lands in pad col
    *reinterpret_cast<float2*>(phi) = make_float2(a1, b1);
}

// ---------- analysis along height, row-pair + col-pair threads ----------
// in (NIMG, HIN, W stride IN_RST) -> lo,hi (NIMG, HOUT, W stride O_RST)
template<int HIN, int W, int IN_IST, int IN_RST, int HOUT,
         int LO_IST, int HI_IST, int O_RST>
__global__ void __launch_bounds__(256)
k_afb_cols(const float* __restrict__ in, float* __restrict__ lo, float* __restrict__ hi)
{
    constexpr int HP = (HOUT + 1) / 2;
    constexpr int WP = (W + 1) / 2;
    int idx = blockIdx.x * 256 + threadIdx.x;
    if (idx >= HP * WP) return;
    int ci = idx % WP;
    int pi = idx / WP;
    int img = blockIdx.y;
    int c2 = 2 * ci;
    int t0 = 2 * pi;
    const float* im = in + (size_t)img * IN_IST + c2;
    int j0 = 2 * t0 - 10;
    float l0x=0,l0y=0,l1x=0,l1y=0,h0x=0,h0y=0,h1x=0,h1y=0;
    if (j0 >= 0 && j0 + 13 < HIN) {
        const float* p = im + (size_t)j0 * IN_RST;
#pragma unroll
        for (int k = 0; k < 14; k++) {
            float2 v = *reinterpret_cast<const float2*>(p + (size_t)k * IN_RST);
            if (k < 12) {
                l0x = fmaf(v.x, c_ana0[k], l0x); l0y = fmaf(v.y, c_ana0[k], l0y);
                h0x = fmaf(v.x, c_ana1[k], h0x); h0y = fmaf(v.y, c_ana1[k], h0y);
            }
            if (k >= 2) {
                l1x = fmaf(v.x, c_ana0[k-2], l1x); l1y = fmaf(v.y, c_ana0[k-2], l1y);
                h1x = fmaf(v.x, c_ana1[k-2], h1x); h1y = fmaf(v.y, c_ana1[k-2], h1y);
            }
        }
    } else {
#pragma unroll
        for (int k = 0; k < 14; k++) {
            int jr = refl(j0 + k, HIN);
            float2 v = *reinterpret_cast<const float2*>(im + (size_t)jr * IN_RST);
            if (k < 12) {
                l0x = fmaf(v.x, c_ana0[k], l0x); l0y = fmaf(v.y, c_ana0[k], l0y);
                h0x = fmaf(v.x, c_ana1[k], h0x); h0y = fmaf(v.y, c_ana1[k], h0y);
            }
            if (k >= 2) {
                l1x = fmaf(v.x, c_ana0[k-2], l1x); l1y = fmaf(v.y, c_ana0[k-2], l1y);
                h1x = fmaf(v.x, c_ana1[k-2], h1x); h1y = fmaf(v.y, c_ana1[k-2], h1y);
            }
        }
    }
    float* plo = lo + (size_t)img * LO_IST + (size_t)t0 * O_RST + c2;
    float* phi = hi + (size_t)img * HI_IST + (size_t)t0 * O_RST + c2;
    *reinterpret_cast<float2*>(plo)          = make_float2(l0x, l0y);
    *reinterpret_cast<float2*>(plo + O_RST)  = make_float2(l1x, l1y);  // pad row if HOUT odd
    *reinterpret_cast<float2*>(phi)          = make_float2(h0x, h0y);
    *reinterpret_cast<float2*>(phi + O_RST)  = make_float2(h1x, h1y);
}

// ---------- synthesis along height: row-pair + float2 cols ----------
// a,b (NIMG, N, W stride RST) -> out (NIMG, 2N-10, W stride O_RST)
template<int N, int W, int A_IST, int A_RST, int B_IST, int B_RST, int O_IST, int O_RST>
__global__ void __launch_bounds__(256)
k_sfb_cols(const float* __restrict__ a, const float* __restrict__ b, float* __restrict__ out)
{
    constexpr int NP = N - 5;
    constexpr int WP = (W + 1) / 2;
    int idx = blockIdx.x * 256 + threadIdx.x;
    if (idx >= NP * WP) return;
    int ci = idx % WP;
    int u  = idx / WP;
    int img = blockIdx.y;
    int c2 = 2 * ci;
    const float* pa = a + (size_t)img * A_IST + (size_t)u * A_RST + c2;
    const float* pb = b + (size_t)img * B_IST + (size_t)u * B_RST + c2;
    float ex=0,ey=0,ox=0,oy=0;
#pragma unroll
    for (int dm = 0; dm < 6; dm++) {
        float2 va = *reinterpret_cast<const float2*>(pa + (size_t)dm * A_RST);
        float2 vb = *reinterpret_cast<const float2*>(pb + (size_t)dm * B_RST);
        float s0e = c_syn0[1 + 2*dm], s1e = c_syn1[1 + 2*dm];
        float s0o = c_syn0[2*dm],     s1o = c_syn1[2*dm];
        ex = fmaf(va.x, s0e, ex); ey = fmaf(va.y, s0e, ey);
        ex = fmaf(vb.x, s1e, ex); ey = fmaf(vb.y, s1e, ey);
        ox = fmaf(va.x, s0o, ox); oy = fmaf(va.y, s0o, oy);
        ox = fmaf(vb.x, s1o, ox); oy = fmaf(vb.y, s1o, oy);
    }
    float* po = out + (size_t)img * O_IST + (size_t)(2 * u) * O_RST + c2;
    *reinterpret_cast<float2*>(po)         = make_float2(ex, ey);
    *reinterpret_cast<float2*>(po + O_RST) = make_float2(ox, oy);
}

// ---------- synthesis along width: output quad per thread ----------
// a,b (NIMG, H, N stride RST) -> out (NIMG, H, NOUT stride O_RST)
template<int H, int N, int A_IST, int A_RST, int B_IST, int B_RST,
         int NOUT, int O_IST, int O_RST>
__global__ void __launch_bounds__(256)
k_sfb_rows(const float* __restrict__ a, const float* __restrict__ b, float* __restrict__ out)
{
    constexpr int NQ = (NOUT + 3) / 4;
    int idx = blockIdx.x * 256 + threadIdx.x;
    if (idx >= H * NQ) return;
    int q = idx % NQ;
    int r = idx / NQ;
    int img = blockIdx.y;
    const float* pa = a + (size_t)img * A_IST + (size_t)r * A_RST + 2 * q;
    const float* pb = b + (size_t)img * B_IST + (size_t)r * B_RST + 2 * q;
    float wa[7], wb[7];
    {
        float2 v0 = *reinterpret_cast<const float2*>(pa);
        float2 v1 = *reinterpret_cast<const float2*>(pa + 2);
        float2 v2 = *reinterpret_cast<const float2*>(pa + 4);
        wa[0]=v0.x; wa[1]=v0.y; wa[2]=v1.x; wa[3]=v1.y; wa[4]=v2.x; wa[5]=v2.y; wa[6]=pa[6];
        float2 u0 = *reinterpret_cast<const float2*>(pb);
        float2 u1 = *reinterpret_cast<const float2*>(pb + 2);
        float2 u2 = *reinterpret_cast<const float2*>(pb + 4);
        wb[0]=u0.x; wb[1]=u0.y; wb[2]=u1.x; wb[3]=u1.y; wb[4]=u2.x; wb[5]=u2.y; wb[6]=pb[6];
    }
    float o0=0,o1=0,o2=0,o3=0;
#pragma unroll
    for (int dm = 0; dm < 6; dm++) {
        float s0e = c_syn0[1 + 2*dm], s1e = c_syn1[1 + 2*dm];
        float s0o = c_syn0[2*dm],     s1o = c_syn1[2*dm];
        o0 = fmaf(wa[dm],     s0e, o0); o0 = fmaf(wb[dm],     s1e, o0);
        o1 = fmaf(wa[dm],     s0o, o1); o1 = fmaf(wb[dm],     s1o, o1);
        o2 = fmaf(wa[dm + 1], s0e, o2); o2 = fmaf(wb[dm + 1], s1e, o2);
        o3 = fmaf(wa[dm + 1], s0o, o3); o3 = fmaf(wb[dm + 1], s1o, o3);
    }
    float* po = out + (size_t)img * O_IST + (size_t)r * O_RST + 4 * q;
    if (4 * q + 3 < NOUT) {
        *reinterpret_cast<float2*>(po)     = make_float2(o0, o1);
        *reinterpret_cast<float2*>(po + 2) = make_float2(o2, o3);
    } else {
        if (4 * q     < NOUT) po[0] = o0;
        if (4 * q + 1 < NOUT) po[1] = o1;
        if (4 * q + 2 < NOUT) po[2] = o2;
        if (4 * q + 3 < NOUT) po[3] = o3;
    }
}

// ---------- per-pixel channel mixing at the coarsest scale ----------
__global__ void __launch_bounds__(256)
k_mix_yl(const float* __restrict__ in, const float* __restrict__ w, float* __restrict__ out)
{
    int idx = blockIdx.x * 256 + threadIdx.x;
    if (idx >= 8 * 32 * 1764) return;
    int p = idx % 1764;
    int o = (idx / 1764) % 32;
    int bB = idx / (1764 * 32);
    float acc = 0.f;
#pragma unroll
    for (int i = 0; i < 32; i++)
        acc = fmaf(in[(bB * 32 + i) * 1764 + p], w[(i * 32 + o) * 1764 + p], acc);
    out[idx] = acc;
}

__global__ void __launch_bounds__(256)
k_mix_yh(const float* __restrict__ in, const float* __restrict__ w, float* __restrict__ out)
{
    int idx = blockIdx.x * 256 + threadIdx.x;
    if (idx >= 8 * 32 * 3 * 1764) return;
    int p = idx % 1764;
    int c = (idx / 1764) % 3;
    int o = (idx / (1764 * 3)) % 32;
    int bB = idx / (1764 * 3 * 32);
    float acc = 0.f;
#pragma unroll
    for (int i = 0; i < 32; i++)
        acc = fmaf(in[((bB * 32 + i) * 3 + c) * 1764 + p],
                   w [((i * 32 + o) * 3 + c) * 1764 + p], acc);
    out[idx] = acc;
}

static inline dim3 grd2(long n) { return dim3((unsigned)((n + 255) / 256), NIMG, 1); }
static inline int  grd1(long n) { return (int)((n + 255) / 256); }

extern "C" void kernel_launch(void* const* d_in, const int* in_sizes, int n_in,
                              void* d_out, int out_size)
{
    const float* x    = (const float*)d_in[0];
    const float* w_yl = (const float*)d_in[1];
    const float* w_yh = (const float*)d_in[2];
    float* out = (float*)d_out;

    float *tmpA, *tmpB, *llA, *llB, *yh1, *yh2, *yh3, *yl4, *yh4, *yl4t, *yh4t;
    cudaGetSymbolAddress((void**)&tmpA, g_tmpA);
    cudaGetSymbolAddress((void**)&tmpB, g_tmpB);
    cudaGetSymbolAddress((void**)&llA,  g_llA);
    cudaGetSymbolAddress((void**)&llB,  g_llB);
    cudaGetSymbolAddress((void**)&yh1,  g_yh1);
    cudaGetSymbolAddress((void**)&yh2,  g_yh2);
    cudaGetSymbolAddress((void**)&yh3,  g_yh3);
    cudaGetSymbolAddress((void**)&yl4,  g_yl4);
    cudaGetSymbolAddress((void**)&yh4,  g_yh4);
    cudaGetSymbolAddress((void**)&yl4t, g_yl4t);
    cudaGetSymbolAddress((void**)&yh4t, g_yh4t);

    // ================= forward DWT =================
    // level 1: 512x512 -> 261x261 (ll rst 262, yh1 rst 262 / sb 68644)
    k_afb_rows<512,512,261, 512*512,512, 262, 512*262><<<grd2(512L*131),256>>>(x, tmpA, tmpB);
    k_afb_cols<512,261, 512*262,262, 261, 68644, 3*68644, 262><<<grd2(131L*131),256>>>(tmpA, llA, yh1);
    k_afb_cols<512,261, 512*262,262, 261, 3*68644, 3*68644, 262><<<grd2(131L*131),256>>>(tmpB, yh1+68644, yh1+2*68644);
    // level 2: 261 -> 136
    k_afb_rows<261,261,136, 68644,262, 136, 262*136><<<grd2(261L*68),256>>>(llA, tmpA, tmpB);
    k_afb_cols<261,136, 262*136,136, 136, 18496, 3*18496, 136><<<grd2(68L*68),256>>>(tmpA, llB, yh2);
    k_afb_cols<261,136, 262*136,136, 136, 3*18496, 3*18496, 136><<<grd2(68L*68),256>>>(tmpB, yh2+18496, yh2+2*18496);
    // level 3: 136 -> 73 (rst 74, sb 5476)
    k_afb_rows<136,136,73, 18496,136, 74, 137*74><<<grd2(136L*37),256>>>(llB, tmpA, tmpB);
    k_afb_cols<136,73, 137*74,74, 73, 5476, 3*5476, 74><<<grd2(37L*37),256>>>(tmpA, llA, yh3);
    k_afb_cols<136,73, 137*74,74, 73, 3*5476, 3*5476, 74><<<grd2(37L*37),256>>>(tmpB, yh3+5476, yh3+2*5476);
    // level 4: 73 -> 42
    k_afb_rows<73,73,42, 5476,74, 42, 75*42><<<grd2(73L*21),256>>>(llA, tmpA, tmpB);
    k_afb_cols<73,42, 75*42,42, 42, 1764, 3*1764, 42><<<grd2(21L*21),256>>>(tmpA, yl4, yh4);
    k_afb_cols<73,42, 75*42,42, 42, 3*1764, 3*1764, 42><<<grd2(21L*21),256>>>(tmpB, yh4+1764, yh4+2*1764);

    // ================= channel mixing =================
    k_mix_yl<<<grd1(8L*32*1764),   256>>>(yl4, w_yl, yl4t);
    k_mix_yh<<<grd1(8L*32*3*1764), 256>>>(yh4, w_yh, yh4t);

    // ================= inverse DWT =================
    // level 4: 42 -> 74x74 (rst 74)
    k_sfb_cols<42,42, 1764,42, 3*1764,42, 75*42,42><<<grd2(37L*21),256>>>(yl4t,      yh4t,        tmpA);
    k_sfb_cols<42,42, 3*1764,42, 3*1764,42, 75*42,42><<<grd2(37L*21),256>>>(yh4t+1764, yh4t+2*1764, tmpB);
    k_sfb_rows<74,42, 75*42,42, 75*42,42, 74, 5476,74><<<grd2(74L*19),256>>>(tmpA, tmpB, llA);
    // level 3: crop 74->73 -> 136x136 (into llB)
    k_sfb_cols<73,73, 5476,74, 3*5476,74, 137*74,74><<<grd2(68L*37),256>>>(llA,      yh3,        tmpA);
    k_sfb_cols<73,73, 3*5476,74, 3*5476,74, 137*74,74><<<grd2(68L*37),256>>>(yh3+5476, yh3+2*5476, tmpB);
    k_sfb_rows<136,73, 137*74,74, 137*74,74, 136, 18496,136><<<grd2(136L*34),256>>>(tmpA, tmpB, llB);
    // level 2: 136 -> 262x262 (into llA, rst 262)
    k_sfb_cols<136,136, 18496,136, 3*18496,136, 263*136,136><<<grd2(131L*68),256>>>(llB,       yh2,         tmpA);
    k_sfb_cols<136,136, 3*18496,136, 3*18496,136, 263*136,136><<<grd2(131L*68),256>>>(yh2+18496, yh2+2*18496, tmpB);
    k_sfb_rows<262,136, 263*136,136, 263*136,136, 262, 68644,262><<<grd2(262L*66),256>>>(tmpA, tmpB, llA);
    // level 1: crop 262->261 -> 512x512 into d_out
    k_sfb_cols<261,261, 68644,262, 3*68644,262, 512*262,262><<<grd2(256L*131),256>>>(llA,       yh1,         tmpA);
    k_sfb_cols<261,261, 3*68644,262, 3*68644,262, 512*262,262><<<grd2(256L*131),256>>>(yh1+68644, yh1+2*68644, tmpB);
    k_sfb_rows<512,261, 512*262,262, 512*262,262, 512, 512*512,512><<<grd2(512L*128),256>>>(tmpA, tmpB, out);
}